// round 11
// baseline (speedup 1.0000x reference)
#include <cuda_runtime.h>
#include <stdint.h>

// GreedyInvasionMemory v6: 512 threads / 16 warps. Replicated scalar decision:
// every warp redundantly computes step t-1's (A,B) at the top of step t from
// parity-buffered slots -- no special warp, no abf broadcast, decision latency
// hidden under phase 1. ku moved to phase 2 (warp 2, from published u[]).
// 2 barriers/step. J + Pqv in registers; Pqq in smem (one RMW pass/step).

#define T_STEPS 2048
#define D 128
#define NT 512
#define NW 16

typedef unsigned long long u64;
struct f2 { u64 v; };

__device__ __forceinline__ f2 mk2(float x, float y) {
    f2 r; asm("mov.b64 %0, {%1, %2};" : "=l"(r.v) : "f"(x), "f"(y)); return r;
}
__device__ __forceinline__ f2 fma2(f2 a, f2 b, f2 c) {
    f2 d; asm("fma.rn.f32x2 %0, %1, %2, %3;" : "=l"(d.v) : "l"(a.v), "l"(b.v), "l"(c.v));
    return d;
}
__device__ __forceinline__ f2 mul2(f2 a, f2 b) {
    f2 d; asm("mul.rn.f32x2 %0, %1, %2;" : "=l"(d.v) : "l"(a.v), "l"(b.v)); return d;
}
__device__ __forceinline__ float sum2(f2 a) {
    float x, y; asm("mov.b64 {%0, %1}, %2;" : "=f"(x), "=f"(y) : "l"(a.v));
    return x + y;
}
__device__ __forceinline__ float wred(float x) {
    x += __shfl_xor_sync(0xffffffffu, x, 16);
    x += __shfl_xor_sync(0xffffffffu, x, 8);
    x += __shfl_xor_sync(0xffffffffu, x, 4);
    x += __shfl_xor_sync(0xffffffffu, x, 2);
    x += __shfl_xor_sync(0xffffffffu, x, 1);
    return x;
}
__device__ __forceinline__ float dot4(float4 a, float4 b) {
    return a.x * b.x + a.y * b.y + a.z * b.z + a.w * b.w;
}
// Reduce 8 per-lane row-partials across the warp; lane L gets row (L & 7).
__device__ __forceinline__ float butterfly8(const float* p, int L) {
    float bb[4];
#pragma unroll
    for (int m = 0; m < 4; m++) {
        const float s = (L & 1) ? p[2 * m] : p[2 * m + 1];
        const float r = __shfl_xor_sync(0xffffffffu, s, 1);
        bb[m] = ((L & 1) ? p[2 * m + 1] : p[2 * m]) + r;
    }
    float cc[2];
#pragma unroll
    for (int m = 0; m < 2; m++) {
        const float s = (L & 2) ? bb[2 * m] : bb[2 * m + 1];
        const float r = __shfl_xor_sync(0xffffffffu, s, 2);
        cc[m] = ((L & 2) ? bb[2 * m + 1] : bb[2 * m]) + r;
    }
    const float s = (L & 4) ? cc[0] : cc[1];
    const float r = __shfl_xor_sync(0xffffffffu, s, 4);
    float wv = ((L & 4) ? cc[1] : cc[0]) + r;
    wv += __shfl_xor_sync(0xffffffffu, wv, 8);
    wv += __shfl_xor_sync(0xffffffffu, wv, 16);
    return wv;
}

struct Smem {
    float Pqq[D * D];            // 64 KB, sum q q^T
    float vecs[3][3][D];         // triple-buffered q/k/v
    u64   vecs2[3][3][D];        // duplicated-pair copies (broadcast operands)
    float u[D];                  // u' = Pqq_{t-1} k_t
    float slot_sl[2][NW];        // phase-1, per warp
    float slot_jqv[2][NW];       // phase-2, per warp
    float slot_jq2[2][NW];
    float slot_mu[2][NW];
    float ku_s[2];               // phase-2, warp 2 scalar
    float qkvv[2][2];            // phase-1, warp 1 scalars
};

// Replicated decision for step tp. ALL warps execute this identically; all
// lanes end with the same (A, B). Doubles replicated. Warp 0 lane 0 writes out.
__device__ __forceinline__ void decide(Smem& S, int tp, int L, int w,
                                       double& T1, double& T2, double& Tvv,
                                       float& t1f, float& t2f,
                                       float& A, float& B,
                                       float* __restrict__ out)
{
    const int par = tp & 1;
    float a1 = (L < NW) ? S.slot_sl[par][L]  : 0.f;
    float a2 = (L < NW) ? S.slot_jqv[par][L] : 0.f;
    float a3 = (L < NW) ? S.slot_jq2[par][L] : 0.f;
    float a4 = (L < NW) ? S.slot_mu[par][L]  : 0.f;
    const float sl  = wred(a1);   // all lanes get the full sums
    const float jqv = wred(a2);
    const float jq2 = wred(a3);
    const float mup = wred(a4);
    const float qk  = S.qkvv[par][0];
    const float vv  = S.qkvv[par][1];
    const float kup = S.ku_s[par];
    const float ku = fmaf(qk, qk, kup);      // k^T Pqq_t k
    const float mu = fmaf(jqv, qk, mup);     // v^T J Pqq_t k

    const float sJs  = t1f + jqv;
    const float AJJr = t2f + jq2;
    const float fl  = (float)(tp + 1);
    const float inv = 1.f / fl;
    const float sJ  = sJs * inv;
    const float AJJ = AJJr * inv;
    const float sl_ = sl * inv;
    const float All = vv * ku * inv;
    const float AJl = mu * inv;
    const bool first = (tp == 0);

    const float AJJs = (first || AJJ == 0.f) ? 1.f : AJJ;
    const float Alls = (first || All == 0.f) ? 1.f : All;
    const float denom = AJJ * All - AJl * AJl;
    const float denoms = (first || denom == 0.f) ? 1.f : denom;
    const float rA = 1.f / AJJs;
    const float rL = 1.f / Alls;
    const float rD = 1.f / denoms;

    const float margin = sl_ - AJl * (sJ * rA);
    const float wf = (All * sJ - AJl * sl_) * rD;
    const float wi = (AJJ * sl_ - AJl * sJ) * rD;
    const float wfc = (wi <= 0.f) ? (sJ * rA) : ((wf <= 0.f) ? 0.f : wf);
    const float wic = (wi <= 0.f) ? 0.f : ((wf <= 0.f) ? (sl_ * rL) : wi);
    const bool dou = margin > 0.f;

    A = first ? 0.f : (dou ? wfc : 1.f);
    B = first ? 1.f : (dou ? wic : 0.f);

    // double bookkeeping, replicated on all lanes (one-step slack before use)
    const double T1p = T1 + (double)jqv;
    const double T2p = T2 + (double)jq2;
    Tvv += (double)vv;
    T1 = (double)A * T1p + (double)B * (double)sl;
    T2 = (double)A * (double)A * T2p
       + 2.0 * (double)A * (double)B * (double)mu
       + (double)B * (double)B * (double)ku * (double)vv;
    t1f = (float)T1; t2f = (float)T2;

    if (w == 0 && L == 0) {
        out[tp]           = (float)(0.5 * Tvv - T1 + 0.5 * T2) * inv;
        out[T_STEPS + tp] = (first || dou) ? 1.f : 0.f;
    }
}

extern __shared__ char smem_raw[];

__global__ void __launch_bounds__(NT, 1)
gim_kernel(const float* __restrict__ qg,
           const float* __restrict__ kg,
           const float* __restrict__ vg,
           float* __restrict__ out)
{
    Smem& S = *reinterpret_cast<Smem*>(smem_raw);
    const int tid = threadIdx.x;
    const int w = tid >> 5;     // warp 0..15, rows w+16j
    const int L = tid & 31;

    // ---- init ----
    {
        const float4 z4 = make_float4(0.f, 0.f, 0.f, 0.f);
        for (int i = tid; i < D * D / 4; i += NT)
            reinterpret_cast<float4*>(S.Pqq)[i] = z4;
    }
    if (tid < 3 * D) {
        const int a = tid >> 7, i = tid & 127;
        const float* src = (a == 0) ? qg : ((a == 1) ? kg : vg);
        const float val = src[i];
        S.vecs[0][a][i] = val;  S.vecs2[0][a][i] = mk2(val, val).v;
        S.vecs[1][a][i] = 0.f;  S.vecs2[1][a][i] = 0ull;
        S.vecs[2][a][i] = 0.f;  S.vecs2[2][a][i] = 0ull;
    }

    f2 Jlo[8], Jhi[8], Pvlo[8], Pvhi[8];
#pragma unroll
    for (int j = 0; j < 8; j++) {
        Jlo[j].v = 0ull; Jhi[j].v = 0ull; Pvlo[j].v = 0ull; Pvhi[j].v = 0ull;
    }
    double T1 = 0.0, T2 = 0.0, Tvv = 0.0;
    float t1f = 0.f, t2f = 0.f;
    float A = 1.f, B = 0.f;          // step-0 J update is a no-op

    int cur = 0, prv = 2, nb = 1;    // rotating buffer indices

    __syncthreads();

    for (int t = 0; t < T_STEPS; ++t) {
        const int par = t & 1;

        // issue next-step prefetch first (threads 128..511 cover 3*128 elems)
        float pref = 0.f; int pa = 0, pi = 0;
        const bool doPref = (tid >= 128) && (t + 1 < T_STEPS);
        if (doPref) {
            const int idx = tid - 128;
            pa = idx >> 7; pi = idx & 127;
            const float* src = (pa == 0) ? qg : ((pa == 1) ? kg : vg);
            pref = __ldg(src + (t + 1) * D + pi);
        }

        // ---- replicated decision for step t-1 (all warps, no barrier) ----
        if (t > 0) decide(S, t - 1, L, w, T1, T2, Tvv, t1f, t2f, A, B, out);

        const ulonglong2 qp = reinterpret_cast<const ulonglong2*>(S.vecs[cur][0])[L];
        const ulonglong2 kp = reinterpret_cast<const ulonglong2*>(S.vecs[cur][1])[L];
        const ulonglong2 vp = reinterpret_cast<const ulonglong2*>(S.vecs[cur][2])[L];
        const f2 qlo{qp.x}, qhi{qp.y}, klo{kp.x}, khi{kp.y}, vlo{vp.x}, vhi{vp.y};

        // ---- phase 1: Pqq RMW + u' row partials; Pqv(reg) upd + sl fold ----
        {
            float pu[8];
            f2 slp2; slp2.v = 0ull;
#pragma unroll
            for (int j = 0; j < 8; j++) {
                const int r = w + 16 * j;
                const f2 q2r{S.vecs2[cur][0][r]};
                const f2 k2r{S.vecs2[cur][1][r]};

                ulonglong2* pqp = reinterpret_cast<ulonglong2*>(&S.Pqq[r * D]) + L;
                ulonglong2 pqv_ = *pqp;
                f2 plo{pqv_.x}, phi{pqv_.y};
                pu[j] = sum2(fma2(phi, khi, mul2(plo, klo)));  // u'_r partial (OLD)
                plo = fma2(q2r, qlo, plo);                     // Pqq += q q^T
                phi = fma2(q2r, qhi, phi);
                *pqp = make_ulonglong2(plo.v, phi.v);

                Pvlo[j] = fma2(q2r, vlo, Pvlo[j]);             // Pqv += q v^T
                Pvhi[j] = fma2(q2r, vhi, Pvhi[j]);
                const f2 d2 = fma2(Pvhi[j], vhi, mul2(Pvlo[j], vlo));
                slp2 = fma2(k2r, d2, slp2);                    // sl fold
            }
            const float uv = butterfly8(pu, L);                // u'_{w+16*(L&7)}
            if (L < 8) S.u[w + 16 * L] = uv;
            const float slp = wred(sum2(slp2));
            if (L == 0) S.slot_sl[par][w] = slp;
            if (w == 1) {
                const float qkp = wred(sum2(fma2(qhi, khi, mul2(qlo, klo))));
                const float vvp = wred(sum2(fma2(vhi, vhi, mul2(vlo, vlo))));
                if (L == 0) { S.qkvv[par][0] = qkp; S.qkvv[par][1] = vvp; }
            }
        }
        // park prefetched values in the idle buffer (no reader until next step)
        if (doPref) {
            S.vecs[nb][pa][pi] = pref;
            S.vecs2[nb][pa][pi] = mk2(pref, pref).v;
        }
        __syncthreads();   // bar1: u[], phase-1 slots visible

        // ---- phase 2: J update (local A,B); jqv/mu folds; ||Jq||^2; ku ----
        {
            const bool skip = (A == 1.f) && (B == 0.f);
            const ulonglong2 up = reinterpret_cast<const ulonglong2*>(S.u)[L];
            const f2 ulo{up.x}, uhi{up.y};
            if (!skip) {
                const f2 A2 = mk2(A, A), B2 = mk2(B, B);
                const ulonglong2 kpp =
                    reinterpret_cast<const ulonglong2*>(S.vecs[prv][1])[L];
                const f2 kplo{kpp.x}, kphi{kpp.y};
#pragma unroll
                for (int j = 0; j < 8; j++) {
                    const int r = w + 16 * j;
                    const f2 vp2{S.vecs2[prv][2][r]};
                    const f2 bv2 = mul2(B2, vp2);
                    Jlo[j] = fma2(A2, Jlo[j], mul2(bv2, kplo));
                    Jhi[j] = fma2(A2, Jhi[j], mul2(bv2, kphi));
                }
            }
            float p[8];
            float jqvp = 0.f, mupp = 0.f;
#pragma unroll
            for (int j = 0; j < 8; j++) {
                const int r = w + 16 * j;
                p[j] = sum2(fma2(Jhi[j], qhi, mul2(Jlo[j], qlo)));      // (Jq)_r part
                const float m = sum2(fma2(Jhi[j], uhi, mul2(Jlo[j], ulo))); // (Ju')_r
                const float vr = S.vecs[cur][2][r];
                jqvp = fmaf(vr, p[j], jqvp);
                mupp = fmaf(vr, m, mupp);
            }
            const float wv = butterfly8(p, L);          // (Jq)_{w+16*(L&7)}
            float g = (L < 8) ? wv * wv : 0.f;
            g += __shfl_xor_sync(0xffffffffu, g, 1);
            g += __shfl_xor_sync(0xffffffffu, g, 2);
            g += __shfl_xor_sync(0xffffffffu, g, 4);
            jqvp = wred(jqvp);
            mupp = wred(mupp);
            if (L == 0) {
                S.slot_jq2[par][w] = g;
                S.slot_jqv[par][w] = jqvp;
                S.slot_mu[par][w]  = mupp;
            }
            if (w == 2) {   // ku' = k^T u' from published u[]
                const float4 k4 = reinterpret_cast<const float4*>(S.vecs[cur][1])[L];
                const float4 u4 = reinterpret_cast<const float4*>(S.u)[L];
                const float kt = wred(dot4(k4, u4));
                if (L == 0) S.ku_s[par] = kt;
            }
        }
        __syncthreads();   // bar2: phase-2 slots + prefetched vectors visible

        const int tmp = prv; prv = cur; cur = nb; nb = tmp;
    }

    // ---- epilogue: final decision (all warps), apply J update, write J ----
    decide(S, T_STEPS - 1, L, w, T1, T2, Tvv, t1f, t2f, A, B, out);
    {
        const f2 A2 = mk2(A, A), B2 = mk2(B, B);
        const int fb = (T_STEPS - 1) % 3;
        const ulonglong2 kpp = reinterpret_cast<const ulonglong2*>(S.vecs[fb][1])[L];
        const f2 kplo{kpp.x}, kphi{kpp.y};
#pragma unroll
        for (int j = 0; j < 8; j++) {
            const int r = w + 16 * j;
            const f2 vp2{S.vecs2[fb][2][r]};
            const f2 bv2 = mul2(B2, vp2);
            const f2 jl = fma2(A2, Jlo[j], mul2(bv2, kplo));
            const f2 jh = fma2(A2, Jhi[j], mul2(bv2, kphi));
            reinterpret_cast<ulonglong2*>(out + 2 * T_STEPS + r * D)[L] =
                make_ulonglong2(jl.v, jh.v);
        }
    }
}

extern "C" void kernel_launch(void* const* d_in, const int* in_sizes, int n_in,
                              void* d_out, int out_size)
{
    const float* q = (const float*)d_in[0];
    const float* k = (const float*)d_in[1];
    const float* v = (const float*)d_in[2];
    float* out = (float*)d_out;
    (void)in_sizes; (void)n_in; (void)out_size;

    cudaFuncSetAttribute(gim_kernel,
                         cudaFuncAttributeMaxDynamicSharedMemorySize,
                         (int)sizeof(Smem));
    gim_kernel<<<1, NT, sizeof(Smem)>>>(q, k, v, out);
}

// round 12
// speedup vs baseline: 1.4707x; 1.4707x over previous
#include <cuda_runtime.h>
#include <stdint.h>

// GreedyInvasionMemory v7: 1024 threads / 32 warps, warp w owns rows {w+32j},
// j=0..3. Same algorithm as v5 (best known): Pqq in smem (one RMW/step),
// J + Pqv in registers as f32x2 pairs, butterfly u' inside the RMW pass,
// warp-0 overlapped scalar decision + smem abf broadcast, warp-2 ku,
// 2 barriers/step, triple-buffered q/k/v. Doubling warps/SMSP (4 -> 8)
// to hide the LDS/SHFL latency chains that bound v5.

#define T_STEPS 2048
#define D 128
#define NT 1024
#define NW 32

typedef unsigned long long u64;
struct f2 { u64 v; };

__device__ __forceinline__ f2 mk2(float x, float y) {
    f2 r; asm("mov.b64 %0, {%1, %2};" : "=l"(r.v) : "f"(x), "f"(y)); return r;
}
__device__ __forceinline__ f2 fma2(f2 a, f2 b, f2 c) {
    f2 d; asm("fma.rn.f32x2 %0, %1, %2, %3;" : "=l"(d.v) : "l"(a.v), "l"(b.v), "l"(c.v));
    return d;
}
__device__ __forceinline__ f2 mul2(f2 a, f2 b) {
    f2 d; asm("mul.rn.f32x2 %0, %1, %2;" : "=l"(d.v) : "l"(a.v), "l"(b.v)); return d;
}
__device__ __forceinline__ float sum2(f2 a) {
    float x, y; asm("mov.b64 {%0, %1}, %2;" : "=f"(x), "=f"(y) : "l"(a.v));
    return x + y;
}
__device__ __forceinline__ float wred(float x) {
    x += __shfl_xor_sync(0xffffffffu, x, 16);
    x += __shfl_xor_sync(0xffffffffu, x, 8);
    x += __shfl_xor_sync(0xffffffffu, x, 4);
    x += __shfl_xor_sync(0xffffffffu, x, 2);
    x += __shfl_xor_sync(0xffffffffu, x, 1);
    return x;
}
__device__ __forceinline__ float dot4(float4 a, float4 b) {
    return a.x * b.x + a.y * b.y + a.z * b.z + a.w * b.w;
}
// Reduce 4 per-lane row-partials across the warp; lane L gets row (L & 3)
// fully reduced. 5 shuffles.
__device__ __forceinline__ float butterfly4(const float* p, int L) {
    float bb[2];
#pragma unroll
    for (int m = 0; m < 2; m++) {
        const float s = (L & 1) ? p[2 * m] : p[2 * m + 1];
        const float r = __shfl_xor_sync(0xffffffffu, s, 1);
        bb[m] = ((L & 1) ? p[2 * m + 1] : p[2 * m]) + r;
    }
    const float s = (L & 2) ? bb[0] : bb[1];
    const float r = __shfl_xor_sync(0xffffffffu, s, 2);
    float wv = ((L & 2) ? bb[1] : bb[0]) + r;
    wv += __shfl_xor_sync(0xffffffffu, wv, 4);
    wv += __shfl_xor_sync(0xffffffffu, wv, 8);
    wv += __shfl_xor_sync(0xffffffffu, wv, 16);
    return wv;
}

struct Smem {
    float Pqq[D * D];            // 64 KB, sum q q^T
    float vecs[3][3][D];         // triple-buffered q/k/v
    u64   vecs2[3][3][D];        // duplicated-pair copies (broadcast operands)
    float u[D];                  // u' = Pqq_{t-1} k_t
    float slot_sl[2][NW];        // phase-1, per warp
    float slot_jqv[2][NW];       // phase-2, per warp
    float slot_jq2[2][NW];
    float slot_mu[2][NW];
    float ku_s[2];               // phase-2, warp 2 scalar
    float qkvv[2][2];            // phase-1, warp 1 scalars
    float abf[2];                // (A, B) deferred J-update coefficients
};

// Scalar phase for step t. Warp 0 only; all lanes participate in the folds.
__device__ __forceinline__ void scalar_phase(Smem& S, int t, int L,
                                             double& T1, double& T2, double& Tvv,
                                             float& t1f, float& t2f,
                                             float* __restrict__ out)
{
    const int par = t & 1;
    const float sl  = wred(S.slot_sl[par][L]);
    const float jqv = wred(S.slot_jqv[par][L]);
    const float jq2 = wred(S.slot_jq2[par][L]);
    const float mup = wred(S.slot_mu[par][L]);
    if (L == 0) {
        const float qk  = S.qkvv[par][0];
        const float vv  = S.qkvv[par][1];
        const float kup = S.ku_s[par];
        const float ku = fmaf(qk, qk, kup);      // k^T Pqq_t k
        const float mu = fmaf(jqv, qk, mup);     // v^T J Pqq_t k

        const float sJs  = t1f + jqv;
        const float AJJr = t2f + jq2;
        const float fl  = (float)(t + 1);
        const float inv = 1.f / fl;
        const float sJ  = sJs * inv;
        const float AJJ = AJJr * inv;
        const float sl_ = sl * inv;
        const float All = vv * ku * inv;
        const float AJl = mu * inv;
        const bool first = (t == 0);

        const float AJJs = (first || AJJ == 0.f) ? 1.f : AJJ;
        const float Alls = (first || All == 0.f) ? 1.f : All;
        const float denom = AJJ * All - AJl * AJl;
        const float denoms = (first || denom == 0.f) ? 1.f : denom;
        const float rA = 1.f / AJJs;
        const float rL = 1.f / Alls;
        const float rD = 1.f / denoms;

        const float margin = sl_ - AJl * (sJ * rA);
        const float wf = (All * sJ - AJl * sl_) * rD;
        const float wi = (AJJ * sl_ - AJl * sJ) * rD;
        const float wfc = (wi <= 0.f) ? (sJ * rA) : ((wf <= 0.f) ? 0.f : wf);
        const float wic = (wi <= 0.f) ? 0.f : ((wf <= 0.f) ? (sl_ * rL) : wi);
        const bool dou = margin > 0.f;

        const float A = first ? 0.f : (dou ? wfc : 1.f);
        const float B = first ? 1.f : (dou ? wic : 0.f);
        S.abf[0] = A; S.abf[1] = B;              // consumed after next bar1

        // double bookkeeping (off the abf critical path)
        const double T1p = T1 + (double)jqv;
        const double T2p = T2 + (double)jq2;
        Tvv += (double)vv;
        T1 = (double)A * T1p + (double)B * (double)sl;
        T2 = (double)A * (double)A * T2p
           + 2.0 * (double)A * (double)B * (double)mu
           + (double)B * (double)B * (double)ku * (double)vv;
        t1f = (float)T1; t2f = (float)T2;

        out[t]           = (float)(0.5 * Tvv - T1 + 0.5 * T2) * inv;
        out[T_STEPS + t] = (first || dou) ? 1.f : 0.f;
    }
}

extern __shared__ char smem_raw[];

__global__ void __launch_bounds__(NT, 1)
gim_kernel(const float* __restrict__ qg,
           const float* __restrict__ kg,
           const float* __restrict__ vg,
           float* __restrict__ out)
{
    Smem& S = *reinterpret_cast<Smem*>(smem_raw);
    const int tid = threadIdx.x;
    const int w = tid >> 5;     // warp 0..31, rows w+32j (j=0..3)
    const int L = tid & 31;

    // ---- init ----
    {
        const float4 z4 = make_float4(0.f, 0.f, 0.f, 0.f);
        for (int i = tid; i < D * D / 4; i += NT)
            reinterpret_cast<float4*>(S.Pqq)[i] = z4;
    }
    if (tid < 3 * D) {
        const int a = tid >> 7, i = tid & 127;
        const float* src = (a == 0) ? qg : ((a == 1) ? kg : vg);
        const float val = src[i];
        S.vecs[0][a][i] = val;  S.vecs2[0][a][i] = mk2(val, val).v;
        S.vecs[1][a][i] = 0.f;  S.vecs2[1][a][i] = 0ull;
        S.vecs[2][a][i] = 0.f;  S.vecs2[2][a][i] = 0ull;
    }
    if (tid == 0) { S.abf[0] = 1.f; S.abf[1] = 0.f; }

    f2 Jlo[4], Jhi[4], Pvlo[4], Pvhi[4];
#pragma unroll
    for (int j = 0; j < 4; j++) {
        Jlo[j].v = 0ull; Jhi[j].v = 0ull; Pvlo[j].v = 0ull; Pvhi[j].v = 0ull;
    }
    double T1 = 0.0, T2 = 0.0, Tvv = 0.0;
    float t1f = 0.f, t2f = 0.f;

    int cur = 0, prv = 2, nb = 1;   // rotating buffer indices

    __syncthreads();

    for (int t = 0; t < T_STEPS; ++t) {
        const int par = t & 1;

        // issue next-step prefetch first (threads 512..895 cover 3*128 elems)
        float pref = 0.f; int pa = 0, pi = 0;
        const bool doPref = (tid >= 512) && (tid < 512 + 3 * D) && (t + 1 < T_STEPS);
        if (doPref) {
            const int idx = tid - 512;
            pa = idx >> 7; pi = idx & 127;
            const float* src = (pa == 0) ? qg : ((pa == 1) ? kg : vg);
            pref = __ldg(src + (t + 1) * D + pi);
        }

        // ---- scalar phase for step t-1 (warp 0), overlapped with phase 1 ----
        if (t > 0 && w == 0) scalar_phase(S, t - 1, L, T1, T2, Tvv, t1f, t2f, out);

        const ulonglong2 qp = reinterpret_cast<const ulonglong2*>(S.vecs[cur][0])[L];
        const ulonglong2 kp = reinterpret_cast<const ulonglong2*>(S.vecs[cur][1])[L];
        const ulonglong2 vp = reinterpret_cast<const ulonglong2*>(S.vecs[cur][2])[L];
        const f2 qlo{qp.x}, qhi{qp.y}, klo{kp.x}, khi{kp.y}, vlo{vp.x}, vhi{vp.y};

        // ---- phase 1: Pqq RMW + u' row partials; Pqv(reg) upd + sl fold ----
        {
            float pu[4];
            f2 slp2; slp2.v = 0ull;
#pragma unroll
            for (int j = 0; j < 4; j++) {
                const int r = w + 32 * j;
                const f2 q2r{S.vecs2[cur][0][r]};
                const f2 k2r{S.vecs2[cur][1][r]};

                ulonglong2* pqp = reinterpret_cast<ulonglong2*>(&S.Pqq[r * D]) + L;
                ulonglong2 pqv_ = *pqp;
                f2 plo{pqv_.x}, phi{pqv_.y};
                pu[j] = sum2(fma2(phi, khi, mul2(plo, klo)));  // u'_r partial (OLD)
                plo = fma2(q2r, qlo, plo);                     // Pqq += q q^T
                phi = fma2(q2r, qhi, phi);
                *pqp = make_ulonglong2(plo.v, phi.v);

                Pvlo[j] = fma2(q2r, vlo, Pvlo[j]);             // Pqv += q v^T
                Pvhi[j] = fma2(q2r, vhi, Pvhi[j]);
                const f2 d2 = fma2(Pvhi[j], vhi, mul2(Pvlo[j], vlo));
                slp2 = fma2(k2r, d2, slp2);                    // sl fold
            }
            const float uv = butterfly4(pu, L);                // u'_{w+32*(L&3)}
            if (L < 4) S.u[w + 32 * L] = uv;
            const float slp = wred(sum2(slp2));
            if (L == 0) S.slot_sl[par][w] = slp;
            if (w == 1) {
                const float qkp = wred(sum2(fma2(qhi, khi, mul2(qlo, klo))));
                const float vvp = wred(sum2(fma2(vhi, vhi, mul2(vlo, vlo))));
                if (L == 0) { S.qkvv[par][0] = qkp; S.qkvv[par][1] = vvp; }
            }
        }
        // park prefetched values in the idle buffer (no reader until next step)
        if (doPref) {
            S.vecs[nb][pa][pi] = pref;
            S.vecs2[nb][pa][pi] = mk2(pref, pref).v;
        }
        __syncthreads();   // bar1: u[], phase-1 slots, abf visible

        // ---- phase 2: J update; jqv/mu per-lane folds; ||Jq||^2; ku ----
        {
            const float af = S.abf[0], bf = S.abf[1];
            const bool skip = (af == 1.f) && (bf == 0.f);
            const ulonglong2 up = reinterpret_cast<const ulonglong2*>(S.u)[L];
            const f2 ulo{up.x}, uhi{up.y};
            if (!skip) {
                const f2 A2 = mk2(af, af), B2 = mk2(bf, bf);
                const ulonglong2 kpp =
                    reinterpret_cast<const ulonglong2*>(S.vecs[prv][1])[L];
                const f2 kplo{kpp.x}, kphi{kpp.y};
#pragma unroll
                for (int j = 0; j < 4; j++) {
                    const int r = w + 32 * j;
                    const f2 vp2{S.vecs2[prv][2][r]};
                    const f2 bv2 = mul2(B2, vp2);
                    Jlo[j] = fma2(A2, Jlo[j], mul2(bv2, kplo));
                    Jhi[j] = fma2(A2, Jhi[j], mul2(bv2, kphi));
                }
            }
            float p[4];
            float jqvp = 0.f, mupp = 0.f;
#pragma unroll
            for (int j = 0; j < 4; j++) {
                const int r = w + 32 * j;
                p[j] = sum2(fma2(Jhi[j], qhi, mul2(Jlo[j], qlo)));      // (Jq)_r part
                const float m = sum2(fma2(Jhi[j], uhi, mul2(Jlo[j], ulo))); // (Ju')_r
                const float vr = S.vecs[cur][2][r];
                jqvp = fmaf(vr, p[j], jqvp);
                mupp = fmaf(vr, m, mupp);
            }
            const float wv = butterfly4(p, L);          // (Jq)_{w+32*(L&3)}
            float g = (L < 4) ? wv * wv : 0.f;
            g += __shfl_xor_sync(0xffffffffu, g, 1);
            g += __shfl_xor_sync(0xffffffffu, g, 2);
            jqvp = wred(jqvp);
            mupp = wred(mupp);
            if (L == 0) {
                S.slot_jq2[par][w] = g;
                S.slot_jqv[par][w] = jqvp;
                S.slot_mu[par][w]  = mupp;
            }
            if (w == 2) {   // ku' = k^T u' from published u[]
                const float4 k4 = reinterpret_cast<const float4*>(S.vecs[cur][1])[L];
                const float4 u4 = reinterpret_cast<const float4*>(S.u)[L];
                const float kt = wred(dot4(k4, u4));
                if (L == 0) S.ku_s[par] = kt;
            }
        }
        __syncthreads();   // bar2: phase-2 slots + prefetched vectors visible

        const int tmp = prv; prv = cur; cur = nb; nb = tmp;
    }

    // ---- epilogue: final scalar phase, apply deferred J update, write J ----
    if (w == 0) scalar_phase(S, T_STEPS - 1, L, T1, T2, Tvv, t1f, t2f, out);
    __syncthreads();
    {
        const float af = S.abf[0], bf = S.abf[1];
        const f2 A2 = mk2(af, af), B2 = mk2(bf, bf);
        const int fb = (T_STEPS - 1) % 3;
        const ulonglong2 kpp = reinterpret_cast<const ulonglong2*>(S.vecs[fb][1])[L];
        const f2 kplo{kpp.x}, kphi{kpp.y};
#pragma unroll
        for (int j = 0; j < 4; j++) {
            const int r = w + 32 * j;
            const f2 vp2{S.vecs2[fb][2][r]};
            const f2 bv2 = mul2(B2, vp2);
            const f2 jl = fma2(A2, Jlo[j], mul2(bv2, kplo));
            const f2 jh = fma2(A2, Jhi[j], mul2(bv2, kphi));
            reinterpret_cast<ulonglong2*>(out + 2 * T_STEPS + r * D)[L] =
                make_ulonglong2(jl.v, jh.v);
        }
    }
}

extern "C" void kernel_launch(void* const* d_in, const int* in_sizes, int n_in,
                              void* d_out, int out_size)
{
    const float* q = (const float*)d_in[0];
    const float* k = (const float*)d_in[1];
    const float* v = (const float*)d_in[2];
    float* out = (float*)d_out;
    (void)in_sizes; (void)n_in; (void)out_size;

    cudaFuncSetAttribute(gim_kernel,
                         cudaFuncAttributeMaxDynamicSharedMemorySize,
                         (int)sizeof(Smem));
    gim_kernel<<<1, NT, sizeof(Smem)>>>(q, k, v, out);
}

// round 14
// speedup vs baseline: 1.9207x; 1.3060x over previous
#include <cuda_runtime.h>
#include <stdint.h>

// GreedyInvasionMemory v8: 512 threads / 16 warps, warp w owns rows {w+16j}.
// ALL THREE matrices (Pqq, Pqv, J) in registers as f32x2 pairs -- zero matrix
// smem traffic. Phase 1 is pure register FMA + one butterfly for u'.
// v5 shell: warp-0 overlapped scalar decision + smem abf broadcast, warp-2 ku,
// 2 barriers/step, triple-buffered q/k/v.
// Register budget @512thr: 128/thread. Persistent: Pqq 32 + J 16 + Pqv 16 = 64.

#define T_STEPS 2048
#define D 128
#define NT 512
#define NW 16

typedef unsigned long long u64;
struct f2 { u64 v; };

__device__ __forceinline__ f2 mk2(float x, float y) {
    f2 r; asm("mov.b64 %0, {%1, %2};" : "=l"(r.v) : "f"(x), "f"(y)); return r;
}
__device__ __forceinline__ f2 fma2(f2 a, f2 b, f2 c) {
    f2 d; asm("fma.rn.f32x2 %0, %1, %2, %3;" : "=l"(d.v) : "l"(a.v), "l"(b.v), "l"(c.v));
    return d;
}
__device__ __forceinline__ f2 mul2(f2 a, f2 b) {
    f2 d; asm("mul.rn.f32x2 %0, %1, %2;" : "=l"(d.v) : "l"(a.v), "l"(b.v)); return d;
}
__device__ __forceinline__ float sum2(f2 a) {
    float x, y; asm("mov.b64 {%0, %1}, %2;" : "=f"(x), "=f"(y) : "l"(a.v));
    return x + y;
}
__device__ __forceinline__ float wred(float x) {
    x += __shfl_xor_sync(0xffffffffu, x, 16);
    x += __shfl_xor_sync(0xffffffffu, x, 8);
    x += __shfl_xor_sync(0xffffffffu, x, 4);
    x += __shfl_xor_sync(0xffffffffu, x, 2);
    x += __shfl_xor_sync(0xffffffffu, x, 1);
    return x;
}
// sums lanes 0..15 into lane 0 (values in lanes >=16 must be zeroed by caller)
__device__ __forceinline__ float wred16(float x) {
    x += __shfl_xor_sync(0xffffffffu, x, 8);
    x += __shfl_xor_sync(0xffffffffu, x, 4);
    x += __shfl_xor_sync(0xffffffffu, x, 2);
    x += __shfl_xor_sync(0xffffffffu, x, 1);
    return x;
}
__device__ __forceinline__ float dot4(float4 a, float4 b) {
    return a.x * b.x + a.y * b.y + a.z * b.z + a.w * b.w;
}
// Reduce 8 per-lane row-partials across the warp; lane L gets row (L & 7).
__device__ __forceinline__ float butterfly8(const float* p, int L) {
    float bb[4];
#pragma unroll
    for (int m = 0; m < 4; m++) {
        const float s = (L & 1) ? p[2 * m] : p[2 * m + 1];
        const float r = __shfl_xor_sync(0xffffffffu, s, 1);
        bb[m] = ((L & 1) ? p[2 * m + 1] : p[2 * m]) + r;
    }
    float cc[2];
#pragma unroll
    for (int m = 0; m < 2; m++) {
        const float s = (L & 2) ? bb[2 * m] : bb[2 * m + 1];
        const float r = __shfl_xor_sync(0xffffffffu, s, 2);
        cc[m] = ((L & 2) ? bb[2 * m + 1] : bb[2 * m]) + r;
    }
    const float s = (L & 4) ? cc[0] : cc[1];
    const float r = __shfl_xor_sync(0xffffffffu, s, 4);
    float wv = ((L & 4) ? cc[1] : cc[0]) + r;
    wv += __shfl_xor_sync(0xffffffffu, wv, 8);
    wv += __shfl_xor_sync(0xffffffffu, wv, 16);
    return wv;
}

struct Smem {
    float vecs[3][3][D];         // triple-buffered q/k/v
    u64   vecs2[3][3][D];        // duplicated-pair copies (broadcast operands)
    float u[D];                  // u' = Pqq_{t-1} k_t
    float slot_sl[2][NW];        // phase-1, per warp
    float slot_jqv[2][NW];       // phase-2, per warp
    float slot_jq2[2][NW];
    float slot_mu[2][NW];
    float ku_s[2];               // phase-2, warp 2 scalar
    float qkvv[2][2];            // phase-1, warp 1 scalars
    float abf[2];                // (A, B) deferred J-update coefficients
};

// Scalar phase for step t. Warp 0 only; all lanes participate in the folds.
__device__ __forceinline__ void scalar_phase(Smem& S, int t, int L,
                                             double& T1, double& T2, double& Tvv,
                                             float& t1f, float& t2f,
                                             float* __restrict__ out)
{
    const int par = t & 1;
    float a1 = (L < NW) ? S.slot_sl[par][L]  : 0.f;
    float a2 = (L < NW) ? S.slot_jqv[par][L] : 0.f;
    float a3 = (L < NW) ? S.slot_jq2[par][L] : 0.f;
    float a4 = (L < NW) ? S.slot_mu[par][L]  : 0.f;
    const float sl  = wred16(a1);
    const float jqv = wred16(a2);
    const float jq2 = wred16(a3);
    const float mup = wred16(a4);
    if (L == 0) {
        const float qk  = S.qkvv[par][0];
        const float vv  = S.qkvv[par][1];
        const float kup = S.ku_s[par];
        const float ku = fmaf(qk, qk, kup);      // k^T Pqq_t k
        const float mu = fmaf(jqv, qk, mup);     // v^T J Pqq_t k

        const float sJs  = t1f + jqv;
        const float AJJr = t2f + jq2;
        const float fl  = (float)(t + 1);
        const float inv = 1.f / fl;
        const float sJ  = sJs * inv;
        const float AJJ = AJJr * inv;
        const float sl_ = sl * inv;
        const float All = vv * ku * inv;
        const float AJl = mu * inv;
        const bool first = (t == 0);

        const float AJJs = (first || AJJ == 0.f) ? 1.f : AJJ;
        const float Alls = (first || All == 0.f) ? 1.f : All;
        const float denom = AJJ * All - AJl * AJl;
        const float denoms = (first || denom == 0.f) ? 1.f : denom;
        const float rA = 1.f / AJJs;
        const float rL = 1.f / Alls;
        const float rD = 1.f / denoms;

        const float margin = sl_ - AJl * (sJ * rA);
        const float wf = (All * sJ - AJl * sl_) * rD;
        const float wi = (AJJ * sl_ - AJl * sJ) * rD;
        const float wfc = (wi <= 0.f) ? (sJ * rA) : ((wf <= 0.f) ? 0.f : wf);
        const float wic = (wi <= 0.f) ? 0.f : ((wf <= 0.f) ? (sl_ * rL) : wi);
        const bool dou = margin > 0.f;

        const float A = first ? 0.f : (dou ? wfc : 1.f);
        const float B = first ? 1.f : (dou ? wic : 0.f);
        S.abf[0] = A; S.abf[1] = B;              // consumed after next bar1

        // double bookkeeping (off the abf critical path)
        const double T1p = T1 + (double)jqv;
        const double T2p = T2 + (double)jq2;
        Tvv += (double)vv;
        T1 = (double)A * T1p + (double)B * (double)sl;
        T2 = (double)A * (double)A * T2p
           + 2.0 * (double)A * (double)B * (double)mu
           + (double)B * (double)B * (double)ku * (double)vv;
        t1f = (float)T1; t2f = (float)T2;

        out[t]           = (float)(0.5 * Tvv - T1 + 0.5 * T2) * inv;
        out[T_STEPS + t] = (first || dou) ? 1.f : 0.f;
    }
}

extern __shared__ char smem_raw[];

__global__ void __launch_bounds__(NT, 1)
gim_kernel(const float* __restrict__ qg,
           const float* __restrict__ kg,
           const float* __restrict__ vg,
           float* __restrict__ out)
{
    Smem& S = *reinterpret_cast<Smem*>(smem_raw);
    const int tid = threadIdx.x;
    const int w = tid >> 5;     // warp 0..15, rows w+16j
    const int L = tid & 31;

    // ---- init ----
    if (tid < 3 * D) {
        const int a = tid >> 7, i = tid & 127;
        const float* src = (a == 0) ? qg : ((a == 1) ? kg : vg);
        const float val = src[i];
        S.vecs[0][a][i] = val;  S.vecs2[0][a][i] = mk2(val, val).v;
        S.vecs[1][a][i] = 0.f;  S.vecs2[1][a][i] = 0ull;
        S.vecs[2][a][i] = 0.f;  S.vecs2[2][a][i] = 0ull;
    }
    if (tid == 0) { S.abf[0] = 1.f; S.abf[1] = 0.f; }

    // ALL matrices in registers (f32x2 pairs): Pqq, Pqv, J rows {w+16j}
    f2 PQlo[8], PQhi[8], Jlo[8], Jhi[8], Pvlo[8], Pvhi[8];
#pragma unroll
    for (int j = 0; j < 8; j++) {
        PQlo[j].v = 0ull; PQhi[j].v = 0ull;
        Jlo[j].v = 0ull;  Jhi[j].v = 0ull;
        Pvlo[j].v = 0ull; Pvhi[j].v = 0ull;
    }
    double T1 = 0.0, T2 = 0.0, Tvv = 0.0;
    float t1f = 0.f, t2f = 0.f;

    int cur = 0, prv = 2, nb = 1;   // rotating buffer indices

    __syncthreads();

    for (int t = 0; t < T_STEPS; ++t) {
        const int par = t & 1;

        // issue next-step prefetch first (threads 128..511 cover 3*128 elems)
        float pref = 0.f; int pa = 0, pi = 0;
        const bool doPref = (tid >= 128) && (t + 1 < T_STEPS);
        if (doPref) {
            const int idx = tid - 128;
            pa = idx >> 7; pi = idx & 127;
            const float* src = (pa == 0) ? qg : ((pa == 1) ? kg : vg);
            pref = __ldg(src + (t + 1) * D + pi);
        }

        // ---- scalar phase for step t-1 (warp 0), overlapped with phase 1 ----
        if (t > 0 && w == 0) scalar_phase(S, t - 1, L, T1, T2, Tvv, t1f, t2f, out);

        const ulonglong2 qp = reinterpret_cast<const ulonglong2*>(S.vecs[cur][0])[L];
        const ulonglong2 kp = reinterpret_cast<const ulonglong2*>(S.vecs[cur][1])[L];
        const ulonglong2 vp = reinterpret_cast<const ulonglong2*>(S.vecs[cur][2])[L];
        const f2 qlo{qp.x}, qhi{qp.y}, klo{kp.x}, khi{kp.y}, vlo{vp.x}, vhi{vp.y};

        // ---- phase 1: register Pqq update + u' partials; Pqv upd + sl fold ----
        {
            float pu[8];
            f2 slp2; slp2.v = 0ull;
#pragma unroll
            for (int j = 0; j < 8; j++) {
                const int r = w + 16 * j;
                const f2 q2r{S.vecs2[cur][0][r]};
                const f2 k2r{S.vecs2[cur][1][r]};

                // u'_r partial from OLD Pqq row, then Pqq += q q^T (registers)
                pu[j] = sum2(fma2(PQhi[j], khi, mul2(PQlo[j], klo)));
                PQlo[j] = fma2(q2r, qlo, PQlo[j]);
                PQhi[j] = fma2(q2r, qhi, PQhi[j]);

                Pvlo[j] = fma2(q2r, vlo, Pvlo[j]);             // Pqv += q v^T
                Pvhi[j] = fma2(q2r, vhi, Pvhi[j]);
                const f2 d2 = fma2(Pvhi[j], vhi, mul2(Pvlo[j], vlo));
                slp2 = fma2(k2r, d2, slp2);                    // sl fold
            }
            const float uv = butterfly8(pu, L);                // u'_{w+16*(L&7)}
            if (L < 8) S.u[w + 16 * L] = uv;
            const float slp = wred(sum2(slp2));
            if (L == 0) S.slot_sl[par][w] = slp;
            if (w == 1) {
                const float qkp = wred(sum2(fma2(qhi, khi, mul2(qlo, klo))));
                const float vvp = wred(sum2(fma2(vhi, vhi, mul2(vlo, vlo))));
                if (L == 0) { S.qkvv[par][0] = qkp; S.qkvv[par][1] = vvp; }
            }
        }
        // park prefetched values in the idle buffer (no reader until next step)
        if (doPref) {
            S.vecs[nb][pa][pi] = pref;
            S.vecs2[nb][pa][pi] = mk2(pref, pref).v;
        }
        __syncthreads();   // bar1: u[], phase-1 slots, abf visible

        // ---- phase 2: J update; jqv/mu per-lane folds; ||Jq||^2; ku ----
        {
            const float af = S.abf[0], bf = S.abf[1];
            const bool skip = (af == 1.f) && (bf == 0.f);
            const ulonglong2 up = reinterpret_cast<const ulonglong2*>(S.u)[L];
            const f2 ulo{up.x}, uhi{up.y};
            if (!skip) {
                const f2 A2 = mk2(af, af), B2 = mk2(bf, bf);
                const ulonglong2 kpp =
                    reinterpret_cast<const ulonglong2*>(S.vecs[prv][1])[L];
                const f2 kplo{kpp.x}, kphi{kpp.y};
#pragma unroll
                for (int j = 0; j < 8; j++) {
                    const int r = w + 16 * j;
                    const f2 vp2{S.vecs2[prv][2][r]};
                    const f2 bv2 = mul2(B2, vp2);
                    Jlo[j] = fma2(A2, Jlo[j], mul2(bv2, kplo));
                    Jhi[j] = fma2(A2, Jhi[j], mul2(bv2, kphi));
                }
            }
            float p[8];
            float jqvp = 0.f, mupp = 0.f;
#pragma unroll
            for (int j = 0; j < 8; j++) {
                const int r = w + 16 * j;
                p[j] = sum2(fma2(Jhi[j], qhi, mul2(Jlo[j], qlo)));      // (Jq)_r part
                const float m = sum2(fma2(Jhi[j], uhi, mul2(Jlo[j], ulo))); // (Ju')_r
                const float vr = S.vecs[cur][2][r];
                jqvp = fmaf(vr, p[j], jqvp);
                mupp = fmaf(vr, m, mupp);
            }
            const float wv = butterfly8(p, L);          // (Jq)_{w+16*(L&7)}
            float g = (L < 8) ? wv * wv : 0.f;
            g += __shfl_xor_sync(0xffffffffu, g, 1);
            g += __shfl_xor_sync(0xffffffffu, g, 2);
            g += __shfl_xor_sync(0xffffffffu, g, 4);
            jqvp = wred(jqvp);
            mupp = wred(mupp);
            if (L == 0) {
                S.slot_jq2[par][w] = g;
                S.slot_jqv[par][w] = jqvp;
                S.slot_mu[par][w]  = mupp;
            }
            if (w == 2) {   // ku' = k^T u' from published u[]
                const float4 k4 = reinterpret_cast<const float4*>(S.vecs[cur][1])[L];
                const float4 u4 = reinterpret_cast<const float4*>(S.u)[L];
                const float kt = wred(dot4(k4, u4));
                if (L == 0) S.ku_s[par] = kt;
            }
        }
        __syncthreads();   // bar2: phase-2 slots + prefetched vectors visible

        const int tmp = prv; prv = cur; cur = nb; nb = tmp;
    }

    // ---- epilogue: final scalar phase, apply deferred J update, write J ----
    if (w == 0) scalar_phase(S, T_STEPS - 1, L, T1, T2, Tvv, t1f, t2f, out);
    __syncthreads();
    {
        const float af = S.abf[0], bf = S.abf[1];
        const f2 A2 = mk2(af, af), B2 = mk2(bf, bf);
        const int fb = (T_STEPS - 1) % 3;
        const ulonglong2 kpp = reinterpret_cast<const ulonglong2*>(S.vecs[fb][1])[L];
        const f2 kplo{kpp.x}, kphi{kpp.y};
#pragma unroll
        for (int j = 0; j < 8; j++) {
            const int r = w + 16 * j;
            const f2 vp2{S.vecs2[fb][2][r]};
            const f2 bv2 = mul2(B2, vp2);
            const f2 jl = fma2(A2, Jlo[j], mul2(bv2, kplo));
            const f2 jh = fma2(A2, Jhi[j], mul2(bv2, kphi));
            reinterpret_cast<ulonglong2*>(out + 2 * T_STEPS + r * D)[L] =
                make_ulonglong2(jl.v, jh.v);
        }
    }
}

extern "C" void kernel_launch(void* const* d_in, const int* in_sizes, int n_in,
                              void* d_out, int out_size)
{
    const float* q = (const float*)d_in[0];
    const float* k = (const float*)d_in[1];
    const float* v = (const float*)d_in[2];
    float* out = (float*)d_out;
    (void)in_sizes; (void)n_in; (void)out_size;

    cudaFuncSetAttribute(gim_kernel,
                         cudaFuncAttributeMaxDynamicSharedMemorySize,
                         (int)sizeof(Smem));
    gim_kernel<<<1, NT, sizeof(Smem)>>>(q, k, v, out);
}